// round 5
// baseline (speedup 1.0000x reference)
#include <cuda_runtime.h>
#include <cuda_bf16.h>
#include <mma.h>
#include <math.h>
#include <stdint.h>

using namespace nvcuda;

// ---------------- problem constants ----------------
#define T_TOK   2048
#define HID     2048
#define NH      16
#define D_NOPE  128
#define D_ROPE  64
#define D_QK    192
#define D_V     128
#define Q_LORA  1536
#define KV_LORA 512
#define QKV_A_N 2112
#define SCALING 0.07216878364870322f   // 192^-0.5

// ---------------- scratch ----------------
__device__ __align__(128) float g_qkv_a [T_TOK * QKV_A_N];
__device__ __align__(128) float g_qn    [T_TOK * Q_LORA];
__device__ __align__(128) float g_kvn   [T_TOK * KV_LORA];
__device__ __align__(128) float g_qbuf  [T_TOK * NH * D_QK];
__device__ __align__(128) float g_kvbuf [T_TOK * NH * 256];
__device__ __align__(128) float g_kpe   [T_TOK * D_ROPE];
__device__ __align__(128) float g_attn  [T_TOK * NH * D_V];
__device__ __align__(128) float g_hid   [T_TOK * HID];
// pre-rounded (tf32) weight copies
__device__ __align__(128) float g_w_a   [HID * QKV_A_N];
__device__ __align__(128) float g_w_qb  [Q_LORA * NH * D_QK];
__device__ __align__(128) float g_w_kvb [KV_LORA * NH * 256];
__device__ __align__(128) float g_w_o   [NH * D_V * HID];

// ---------------- helpers ----------------
__device__ __forceinline__ void cp16(void* s, const void* g) {
    unsigned int sa = (unsigned int)__cvta_generic_to_shared(s);
    asm volatile("cp.async.cg.shared.global [%0], [%1], 16;" :: "r"(sa), "l"(g));
}
#define CP_COMMIT() asm volatile("cp.async.commit_group;")
#define CP_WAIT1()  asm volatile("cp.async.wait_group 1;")
#define CP_WAIT0()  asm volatile("cp.async.wait_group 0;")

__device__ __forceinline__ float rnd_tf32(float x) {
    unsigned int u;
    asm("cvt.rna.tf32.f32 %0, %1;" : "=r"(u) : "f"(x));
    return __uint_as_float(u);
}
__device__ __forceinline__ void mma_tf32(float* c,
    unsigned int a0, unsigned int a1, unsigned int a2, unsigned int a3,
    unsigned int b0, unsigned int b1)
{
    asm volatile(
        "mma.sync.aligned.m16n8k8.row.col.f32.tf32.tf32.f32 "
        "{%0,%1,%2,%3},{%4,%5,%6,%7},{%8,%9},{%0,%1,%2,%3};"
        : "+f"(c[0]), "+f"(c[1]), "+f"(c[2]), "+f"(c[3])
        : "r"(a0), "r"(a1), "r"(a2), "r"(a3), "r"(b0), "r"(b1));
}

// ---------------- rounding pass (fp32 -> tf32-valued fp32) ----------------
__global__ __launch_bounds__(256) void round_tf32_kernel(
    const float4* __restrict__ src, float4* __restrict__ dst, int n4)
{
    int i = blockIdx.x * 256 + threadIdx.x;
    const int stride = gridDim.x * 256;
    for (; i < n4; i += stride) {
        float4 v = src[i];
        v.x = rnd_tf32(v.x); v.y = rnd_tf32(v.y);
        v.z = rnd_tf32(v.z); v.w = rnd_tf32(v.w);
        dst[i] = v;
    }
}

// ---------------- tf32 wmma GEMM: C[M,N] = A[M,K] @ B[K,N] ----------------
// Inputs MUST be pre-rounded to tf32 values. BM=256, BN=64, BK=16,
// 8 warps (4m x 2n), warp tile 64x32.
#define GBM 256
#define GBN 64
#define GBK 16
#define LDA_S 20
#define LDB_S 68
#define GEMM_SMEM_BYTES ((2 * GBM * LDA_S + 2 * GBK * LDB_S) * 4)

typedef wmma::fragment<wmma::matrix_a, 16, 16, 8, wmma::precision::tf32, wmma::row_major> FragA;
typedef wmma::fragment<wmma::matrix_b, 16, 16, 8, wmma::precision::tf32, wmma::row_major> FragB;
typedef wmma::fragment<wmma::accumulator, 16, 16, 8, float> FragC;

__global__ __launch_bounds__(256, 2) void tc_gemm(
    const float* __restrict__ A, const float* __restrict__ B,
    float* __restrict__ C, int M, int N, int K, int round_out)
{
    extern __shared__ float smg[];
    float* sA = smg;
    float* sB = smg + 2 * GBM * LDA_S;

    const int tid  = threadIdx.x;
    const int warp = tid >> 5;
    const int wm   = warp >> 1;
    const int wn   = warp & 1;
    const int row0 = blockIdx.y * GBM;
    const int col0 = blockIdx.x * GBN;

    FragC acc[4][2];
#pragma unroll
    for (int i = 0; i < 4; i++)
#pragma unroll
        for (int j = 0; j < 2; j++) wmma::fill_fragment(acc[i][j], 0.f);

    const int ar  = tid >> 2;
    const int ac4 = (tid & 3) << 2;
    const int br  = tid >> 4;
    const int bc4 = (tid & 15) << 2;

    const float* Abase = A + (size_t)(row0 + ar) * K + ac4;
    const float* Bbase = B + (size_t)br * N + col0 + bc4;

#pragma unroll
    for (int j = 0; j < 4; j++)
        cp16(&sA[(ar + 64 * j) * LDA_S + ac4], Abase + (size_t)(64 * j) * K);
    cp16(&sB[br * LDB_S + bc4], Bbase);
    CP_COMMIT();

    int buf = 0;
    for (int k0 = 0; k0 < K; k0 += GBK) {
        if (k0 + GBK < K) {
            const int nb = buf ^ 1;
#pragma unroll
            for (int j = 0; j < 4; j++)
                cp16(&sA[nb * GBM * LDA_S + (ar + 64 * j) * LDA_S + ac4],
                     Abase + (size_t)(64 * j) * K + k0 + GBK);
            cp16(&sB[nb * GBK * LDB_S + br * LDB_S + bc4],
                 Bbase + (size_t)(k0 + GBK) * N);
            CP_COMMIT();
            CP_WAIT1();
        } else {
            CP_WAIT0();
        }
        __syncthreads();

        const float* cA = sA + buf * GBM * LDA_S;
        const float* cB = sB + buf * GBK * LDB_S;
#pragma unroll
        for (int kk = 0; kk < GBK; kk += 8) {
            FragA af[4];
            FragB bf[2];
#pragma unroll
            for (int i = 0; i < 4; i++)
                wmma::load_matrix_sync(af[i], cA + (wm * 64 + i * 16) * LDA_S + kk, LDA_S);
#pragma unroll
            for (int j = 0; j < 2; j++)
                wmma::load_matrix_sync(bf[j], cB + kk * LDB_S + wn * 32 + j * 16, LDB_S);
#pragma unroll
            for (int i = 0; i < 4; i++)
#pragma unroll
                for (int j = 0; j < 2; j++)
                    wmma::mma_sync(acc[i][j], af[i], bf[j], acc[i][j]);
        }
        __syncthreads();
        buf ^= 1;
    }

    if (round_out) {
#pragma unroll
        for (int i = 0; i < 4; i++)
#pragma unroll
            for (int j = 0; j < 2; j++)
#pragma unroll
                for (int e = 0; e < acc[i][j].num_elements; e++)
                    acc[i][j].x[e] = rnd_tf32(acc[i][j].x[e]);
    }
#pragma unroll
    for (int i = 0; i < 4; i++)
#pragma unroll
        for (int j = 0; j < 2; j++)
            wmma::store_matrix_sync(
                C + (size_t)(row0 + wm * 64 + i * 16) * N + col0 + wn * 32 + j * 16,
                acc[i][j], N, wmma::mem_row_major);
}

// ---------------- RMSNorm (output rounded to tf32 values) ----------------
__global__ __launch_bounds__(256) void rmsnorm_kernel(
    const float* __restrict__ in, int ld, int off, int width,
    const float* __restrict__ gamma, float* __restrict__ out)
{
    const int row = blockIdx.x;
    const float* x = in + (size_t)row * ld + off;
    float ss = 0.f;
    for (int i = threadIdx.x; i < width; i += 256) {
        float v = x[i];
        ss += v * v;
    }
#pragma unroll
    for (int o = 16; o; o >>= 1) ss += __shfl_xor_sync(0xffffffffu, ss, o);
    __shared__ float warp_s[8];
    __shared__ float s_inv;
    if ((threadIdx.x & 31) == 0) warp_s[threadIdx.x >> 5] = ss;
    __syncthreads();
    if (threadIdx.x == 0) {
        float t = 0.f;
#pragma unroll
        for (int i = 0; i < 8; i++) t += warp_s[i];
        s_inv = rsqrtf(t / (float)width + 1e-6f);
    }
    __syncthreads();
    const float inv = s_inv;
    float* o = out + (size_t)row * width;
    for (int i = threadIdx.x; i < width; i += 256)
        o[i] = rnd_tf32(x[i] * inv * gamma[i]);
}

// ---------------- RoPE (outputs rounded) ----------------
__global__ __launch_bounds__(256) void rope_kernel(
    float* __restrict__ q, const float* __restrict__ qkv_a,
    float* __restrict__ kpe, const int* __restrict__ positions)
{
    const int t = blockIdx.x;
    const float pos = (float)positions[t];
    for (int i = threadIdx.x; i < NH * 32 + 32; i += 256) {
        if (i < NH * 32) {
            const int h = i >> 5, p = i & 31;
            const float inv = powf(10000.0f, -(float)p / 32.0f);
            float s, c;
            sincosf(pos * inv, &s, &c);
            float* base = q + (size_t)t * (NH * D_QK) + h * D_QK + D_NOPE;
            const float x1 = base[2 * p], x2 = base[2 * p + 1];
            base[2 * p]     = rnd_tf32(x1 * c - x2 * s);
            base[2 * p + 1] = rnd_tf32(x1 * s + x2 * c);
        } else {
            const int p = i - NH * 32;
            const float inv = powf(10000.0f, -(float)p / 32.0f);
            float s, c;
            sincosf(pos * inv, &s, &c);
            const float* src = qkv_a + (size_t)t * QKV_A_N + (Q_LORA + KV_LORA);
            const float x1 = src[2 * p], x2 = src[2 * p + 1];
            kpe[(size_t)t * D_ROPE + 2 * p]     = rnd_tf32(x1 * c - x2 * s);
            kpe[(size_t)t * D_ROPE + 2 * p + 1] = rnd_tf32(x1 * s + x2 * c);
        }
    }
}

// ---------------- tensor-core causal flash attention ----------------
// All inputs pre-rounded tf32; inner loops are pure LDS + HMMA.
#define AT_LDQ 196
#define AT_LDV 136
#define AT_LDP 68
#define AT_SMEM_FLOATS (64*AT_LDQ + 64*AT_LDQ + 64*AT_LDV + 64*AT_LDP + 128 + 128 + 64 + 64 + 64)

__global__ __launch_bounds__(256, 1) void attn_tc_kernel(
    const float* __restrict__ q, const float* __restrict__ kv,
    const float* __restrict__ kpe, float* __restrict__ out)
{
    extern __shared__ float sm[];
    float* sQ     = sm;
    float* sK     = sQ + 64 * AT_LDQ;
    float* sV     = sK + 64 * AT_LDQ;
    float* sP     = sV + 64 * AT_LDV;
    float* sWmax  = sP + 64 * AT_LDP;
    float* sWsum  = sWmax + 128;
    float* sM     = sWsum + 128;
    float* sL     = sM + 64;
    float* sScale = sL + 64;

    const int h   = blockIdx.y;
    const int qt  = blockIdx.x;
    const int t0  = qt * 64;
    const int tid = threadIdx.x;
    const int w   = tid >> 5;
    const int lane = tid & 31;
    const int g   = lane >> 2;
    const int t   = lane & 3;
    const int mrow = (w & 3) * 16;
    const int nhalf = w >> 2;
    const int r0 = mrow + g, r1 = r0 + 8;

    for (int i = tid; i < 64 * 192; i += 256) {
        const int r = i / 192, d = i - r * 192;
        sQ[r * AT_LDQ + d] = q[(size_t)(t0 + r) * (NH * D_QK) + h * D_QK + d];
    }
    if (tid < 64) { sM[tid] = -1e30f; sL[tid] = 0.f; }

    float o[8][4];
#pragma unroll
    for (int i = 0; i < 8; i++)
#pragma unroll
        for (int j = 0; j < 4; j++) o[i][j] = 0.f;

    for (int kt = 0; kt <= qt; kt++) {
        const int k0 = kt * 64;
        __syncthreads();
        for (int i = tid; i < 64 * 192; i += 256) {
            const int r = i / 192, d = i - r * 192;
            sK[r * AT_LDQ + d] = (d < 128)
                ? kv[(size_t)(k0 + r) * (NH * 256) + h * 256 + d]
                : kpe[(size_t)(k0 + r) * D_ROPE + (d - 128)];
        }
        for (int i = tid; i < 64 * 128; i += 256) {
            const int r = i >> 7, d = i & 127;
            sV[r * AT_LDV + d] = kv[(size_t)(k0 + r) * (NH * 256) + h * 256 + 128 + d];
        }
        __syncthreads();

        // ---- S = Q @ K^T ----
        float s[4][4];
#pragma unroll
        for (int nt = 0; nt < 4; nt++)
#pragma unroll
            for (int j = 0; j < 4; j++) s[nt][j] = 0.f;

        const float* qb = sQ + r0 * AT_LDQ + t;
#pragma unroll 4
        for (int kk = 0; kk < 192; kk += 8) {
            const unsigned int a0 = __float_as_uint(qb[kk]);
            const unsigned int a1 = __float_as_uint(qb[8 * AT_LDQ + kk]);
            const unsigned int a2 = __float_as_uint(qb[kk + 4]);
            const unsigned int a3 = __float_as_uint(qb[8 * AT_LDQ + kk + 4]);
#pragma unroll
            for (int nt = 0; nt < 4; nt++) {
                const int key = nhalf * 32 + nt * 8 + g;
                const unsigned int b0 = __float_as_uint(sK[key * AT_LDQ + kk + t]);
                const unsigned int b1 = __float_as_uint(sK[key * AT_LDQ + kk + t + 4]);
                mma_tf32(s[nt], a0, a1, a2, a3, b0, b1);
            }
        }

        const int rg0 = t0 + r0, rg1 = t0 + r1;
#pragma unroll
        for (int nt = 0; nt < 4; nt++) {
            const int cg = k0 + nhalf * 32 + nt * 8 + 2 * t;
            s[nt][0] = (rg0 >= cg)     ? s[nt][0] * SCALING : -1e30f;
            s[nt][1] = (rg0 >= cg + 1) ? s[nt][1] * SCALING : -1e30f;
            s[nt][2] = (rg1 >= cg)     ? s[nt][2] * SCALING : -1e30f;
            s[nt][3] = (rg1 >= cg + 1) ? s[nt][3] * SCALING : -1e30f;
        }

        float mx0 = -1e30f, mx1 = -1e30f;
#pragma unroll
        for (int nt = 0; nt < 4; nt++) {
            mx0 = fmaxf(mx0, fmaxf(s[nt][0], s[nt][1]));
            mx1 = fmaxf(mx1, fmaxf(s[nt][2], s[nt][3]));
        }
        mx0 = fmaxf(mx0, __shfl_xor_sync(0xffffffffu, mx0, 1));
        mx0 = fmaxf(mx0, __shfl_xor_sync(0xffffffffu, mx0, 2));
        mx1 = fmaxf(mx1, __shfl_xor_sync(0xffffffffu, mx1, 1));
        mx1 = fmaxf(mx1, __shfl_xor_sync(0xffffffffu, mx1, 2));
        if (t == 0) { sWmax[nhalf * 64 + r0] = mx0; sWmax[nhalf * 64 + r1] = mx1; }
        __syncthreads();

        const float mn0 = fmaxf(sM[r0], fmaxf(sWmax[r0], sWmax[64 + r0]));
        const float mn1 = fmaxf(sM[r1], fmaxf(sWmax[r1], sWmax[64 + r1]));

        float sum0 = 0.f, sum1 = 0.f;
#pragma unroll
        for (int nt = 0; nt < 4; nt++) {
            s[nt][0] = __expf(s[nt][0] - mn0);
            s[nt][1] = __expf(s[nt][1] - mn0);
            s[nt][2] = __expf(s[nt][2] - mn1);
            s[nt][3] = __expf(s[nt][3] - mn1);
            sum0 += s[nt][0] + s[nt][1];
            sum1 += s[nt][2] + s[nt][3];
            const int coll = nhalf * 32 + nt * 8 + 2 * t;
            *(float2*)(sP + r0 * AT_LDP + coll) =
                make_float2(rnd_tf32(s[nt][0]), rnd_tf32(s[nt][1]));
            *(float2*)(sP + r1 * AT_LDP + coll) =
                make_float2(rnd_tf32(s[nt][2]), rnd_tf32(s[nt][3]));
        }
        sum0 += __shfl_xor_sync(0xffffffffu, sum0, 1);
        sum0 += __shfl_xor_sync(0xffffffffu, sum0, 2);
        sum1 += __shfl_xor_sync(0xffffffffu, sum1, 1);
        sum1 += __shfl_xor_sync(0xffffffffu, sum1, 2);
        if (t == 0) { sWsum[nhalf * 64 + r0] = sum0; sWsum[nhalf * 64 + r1] = sum1; }
        __syncthreads();

        if (tid < 64) {
            const float mo = sM[tid];
            const float mn = fmaxf(mo, fmaxf(sWmax[tid], sWmax[64 + tid]));
            const float sc = __expf(mo - mn);
            sM[tid] = mn;
            sL[tid] = sL[tid] * sc + sWsum[tid] + sWsum[64 + tid];
            sScale[tid] = sc;
        }
        __syncthreads();

        const float sc0 = sScale[r0], sc1 = sScale[r1];
#pragma unroll
        for (int nt = 0; nt < 8; nt++) {
            o[nt][0] *= sc0; o[nt][1] *= sc0;
            o[nt][2] *= sc1; o[nt][3] *= sc1;
        }

        // ---- O += P @ V ----
        const float* pb = sP + r0 * AT_LDP + t;
#pragma unroll 2
        for (int kk = 0; kk < 64; kk += 8) {
            const unsigned int a0 = __float_as_uint(pb[kk]);
            const unsigned int a1 = __float_as_uint(pb[8 * AT_LDP + kk]);
            const unsigned int a2 = __float_as_uint(pb[kk + 4]);
            const unsigned int a3 = __float_as_uint(pb[8 * AT_LDP + kk + 4]);
#pragma unroll
            for (int nt = 0; nt < 8; nt++) {
                const int nc = nhalf * 64 + nt * 8 + g;
                const unsigned int b0 = __float_as_uint(sV[(kk + t) * AT_LDV + nc]);
                const unsigned int b1 = __float_as_uint(sV[(kk + t + 4) * AT_LDV + nc]);
                mma_tf32(o[nt], a0, a1, a2, a3, b0, b1);
            }
        }
    }

    const float il0 = 1.f / sL[r0];
    const float il1 = 1.f / sL[r1];
#pragma unroll
    for (int nt = 0; nt < 8; nt++) {
        const int col = h * D_V + nhalf * 64 + nt * 8 + 2 * t;
        *(float2*)(out + (size_t)(t0 + r0) * (NH * D_V) + col) =
            make_float2(rnd_tf32(o[nt][0] * il0), rnd_tf32(o[nt][1] * il0));
        *(float2*)(out + (size_t)(t0 + r1) * (NH * D_V) + col) =
            make_float2(rnd_tf32(o[nt][2] * il1), rnd_tf32(o[nt][3] * il1));
    }
}

// ---------------- launch ----------------
extern "C" void kernel_launch(void* const* d_in, const int* in_sizes, int n_in,
                              void* d_out, int out_size)
{
    const float* hidden    = (const float*)d_in[0];
    const int*   positions = (const int*)  d_in[1];
    const float* w_qkv_a   = (const float*)d_in[2];
    const float* gamma_q   = (const float*)d_in[3];
    const float* w_q_b     = (const float*)d_in[4];
    const float* gamma_kv  = (const float*)d_in[5];
    const float* w_kv_b    = (const float*)d_in[6];
    const float* w_o       = (const float*)d_in[7];
    float* out = (float*)d_out;

    float *qkv_a, *qn, *kvn, *qbuf, *kvbuf, *kpe, *attn, *hid;
    float *wa, *wqb, *wkvb, *wo;
    cudaGetSymbolAddress((void**)&qkv_a, g_qkv_a);
    cudaGetSymbolAddress((void**)&qn,    g_qn);
    cudaGetSymbolAddress((void**)&kvn,   g_kvn);
    cudaGetSymbolAddress((void**)&qbuf,  g_qbuf);
    cudaGetSymbolAddress((void**)&kvbuf, g_kvbuf);
    cudaGetSymbolAddress((void**)&kpe,   g_kpe);
    cudaGetSymbolAddress((void**)&attn,  g_attn);
    cudaGetSymbolAddress((void**)&hid,   g_hid);
    cudaGetSymbolAddress((void**)&wa,    g_w_a);
    cudaGetSymbolAddress((void**)&wqb,   g_w_qb);
    cudaGetSymbolAddress((void**)&wkvb,  g_w_kvb);
    cudaGetSymbolAddress((void**)&wo,    g_w_o);

    cudaFuncSetAttribute(tc_gemm, cudaFuncAttributeMaxDynamicSharedMemorySize, GEMM_SMEM_BYTES);
    const int attn_smem = AT_SMEM_FLOATS * (int)sizeof(float);
    cudaFuncSetAttribute(attn_tc_kernel, cudaFuncAttributeMaxDynamicSharedMemorySize, attn_smem);

    // 0) round inputs/weights to tf32 values (grid-stride, 592 blocks)
    round_tf32_kernel<<<592, 256>>>((const float4*)hidden,  (float4*)hid,  T_TOK * HID / 4);
    round_tf32_kernel<<<592, 256>>>((const float4*)w_qkv_a, (float4*)wa,   HID * QKV_A_N / 4);
    round_tf32_kernel<<<592, 256>>>((const float4*)w_q_b,   (float4*)wqb,  Q_LORA * NH * D_QK / 4);
    round_tf32_kernel<<<592, 256>>>((const float4*)w_kv_b,  (float4*)wkvb, KV_LORA * NH * 256 / 4);
    round_tf32_kernel<<<592, 256>>>((const float4*)w_o,     (float4*)wo,   NH * D_V * HID / 4);

    // 1) qkv_a = hid @ wa (rounded out)
    tc_gemm<<<dim3(QKV_A_N / GBN, T_TOK / GBM), 256, GEMM_SMEM_BYTES>>>(
        hid, wa, qkv_a, T_TOK, QKV_A_N, HID, 1);

    // 2) RMSNorm (rounded out)
    rmsnorm_kernel<<<T_TOK, 256>>>(qkv_a, QKV_A_N, 0,      Q_LORA,  gamma_q,  qn);
    rmsnorm_kernel<<<T_TOK, 256>>>(qkv_a, QKV_A_N, Q_LORA, KV_LORA, gamma_kv, kvn);

    // 3) q = qn @ wqb (rounded out)
    tc_gemm<<<dim3((NH * D_QK) / GBN, T_TOK / GBM), 256, GEMM_SMEM_BYTES>>>(
        qn, wqb, qbuf, T_TOK, NH * D_QK, Q_LORA, 1);

    // 4) kv = kvn @ wkvb (rounded out)
    tc_gemm<<<dim3((NH * 256) / GBN, T_TOK / GBM), 256, GEMM_SMEM_BYTES>>>(
        kvn, wkvb, kvbuf, T_TOK, NH * 256, KV_LORA, 1);

    // 5) RoPE (rounded out)
    rope_kernel<<<T_TOK, 256>>>(qbuf, qkv_a, kpe, positions);

    // 6) attention (rounded out)
    attn_tc_kernel<<<dim3(T_TOK / 64, NH), 256, attn_smem>>>(qbuf, kvbuf, kpe, attn);

    // 7) out = attn @ wo (full fp32 out)
    tc_gemm<<<dim3(HID / GBN, T_TOK / GBM), 256, GEMM_SMEM_BYTES>>>(
        attn, wo, out, T_TOK, HID, NH * D_V, 0);
}

// round 7
// speedup vs baseline: 1.1658x; 1.1658x over previous
#include <cuda_runtime.h>
#include <cuda_bf16.h>
#include <math.h>
#include <stdint.h>

// ---------------- problem constants ----------------
#define T_TOK   2048
#define HID     2048
#define NH      16
#define D_NOPE  128
#define D_ROPE  64
#define D_QK    192
#define D_V     128
#define Q_LORA  1536
#define KV_LORA 512
#define QKV_A_N 2112
#define SCALING 0.07216878364870322f   // 192^-0.5

// ---------------- scratch ----------------
__device__ __align__(128) float g_qkv_a [T_TOK * QKV_A_N];
__device__ __align__(128) float g_qbuf  [T_TOK * NH * D_QK];
__device__ __align__(128) float g_kvbuf [T_TOK * NH * 256];
__device__ __align__(128) float g_kpe   [T_TOK * D_ROPE];
// bf16 hi/lo planes (K-major for all GEMM operands)
__device__ __align__(128) __nv_bfloat16 g_hid_hi [T_TOK * HID];
__device__ __align__(128) __nv_bfloat16 g_hid_lo [T_TOK * HID];
__device__ __align__(128) __nv_bfloat16 g_qn_hi  [T_TOK * Q_LORA];
__device__ __align__(128) __nv_bfloat16 g_qn_lo  [T_TOK * Q_LORA];
__device__ __align__(128) __nv_bfloat16 g_kvn_hi [T_TOK * KV_LORA];
__device__ __align__(128) __nv_bfloat16 g_kvn_lo [T_TOK * KV_LORA];
__device__ __align__(128) __nv_bfloat16 g_attn_hi[T_TOK * NH * D_V];
__device__ __align__(128) __nv_bfloat16 g_attn_lo[T_TOK * NH * D_V];
__device__ __align__(128) __nv_bfloat16 g_wa_hi  [QKV_A_N * HID];
__device__ __align__(128) __nv_bfloat16 g_wa_lo  [QKV_A_N * HID];
__device__ __align__(128) __nv_bfloat16 g_wqb_hi [NH * D_QK * Q_LORA];
__device__ __align__(128) __nv_bfloat16 g_wqb_lo [NH * D_QK * Q_LORA];
__device__ __align__(128) __nv_bfloat16 g_wkvb_hi[NH * 256 * KV_LORA];
__device__ __align__(128) __nv_bfloat16 g_wkvb_lo[NH * 256 * KV_LORA];
__device__ __align__(128) __nv_bfloat16 g_wo_hi  [HID * NH * D_V];
__device__ __align__(128) __nv_bfloat16 g_wo_lo  [HID * NH * D_V];

// ---------------- helpers ----------------
__device__ __forceinline__ void cp16(void* s, const void* g) {
    unsigned int sa = (unsigned int)__cvta_generic_to_shared(s);
    asm volatile("cp.async.cg.shared.global [%0], [%1], 16;" :: "r"(sa), "l"(g));
}
#define CP_COMMIT() asm volatile("cp.async.commit_group;")
#define CP_WAIT1()  asm volatile("cp.async.wait_group 1;")
#define CP_WAIT0()  asm volatile("cp.async.wait_group 0;")

__device__ __forceinline__ uint32_t smem_u32(const void* p) {
    return (uint32_t)__cvta_generic_to_shared(p);
}
#define LDSM4(r0, r1, r2, r3, a) \
    asm volatile("ldmatrix.sync.aligned.m8n8.x4.shared.b16 {%0,%1,%2,%3}, [%4];" \
        : "=r"(r0), "=r"(r1), "=r"(r2), "=r"(r3) : "r"(a))

__device__ __forceinline__ void mma_bf16(float* c,
    uint32_t a0, uint32_t a1, uint32_t a2, uint32_t a3, uint32_t b0, uint32_t b1)
{
    asm volatile(
        "mma.sync.aligned.m16n8k16.row.col.f32.bf16.bf16.f32 "
        "{%0,%1,%2,%3},{%4,%5,%6,%7},{%8,%9},{%0,%1,%2,%3};"
        : "+f"(c[0]), "+f"(c[1]), "+f"(c[2]), "+f"(c[3])
        : "r"(a0), "r"(a1), "r"(a2), "r"(a3), "r"(b0), "r"(b1));
}

__device__ __forceinline__ void split_hl(float v, __nv_bfloat16& h, __nv_bfloat16& l) {
    h = __float2bfloat16(v);
    l = __float2bfloat16(v - __bfloat162float(h));
}

// ---------------- converters ----------------
__global__ __launch_bounds__(256) void convert_hl_kernel(
    const float2* __restrict__ src, uint32_t* __restrict__ hi,
    uint32_t* __restrict__ lo, int n2)
{
    int i = blockIdx.x * 256 + threadIdx.x;
    const int stride = gridDim.x * 256;
    for (; i < n2; i += stride) {
        const float2 v = src[i];
        __nv_bfloat16 h0, l0, h1, l1;
        split_hl(v.x, h0, l0);
        split_hl(v.y, h1, l1);
        hi[i] = (uint32_t)__bfloat16_as_ushort(h0) | ((uint32_t)__bfloat16_as_ushort(h1) << 16);
        lo[i] = (uint32_t)__bfloat16_as_ushort(l0) | ((uint32_t)__bfloat16_as_ushort(l1) << 16);
    }
}

// in fp32 [R][C] -> out hi/lo bf16 [C][R]
__global__ __launch_bounds__(256) void transpose_cvt_kernel(
    const float* __restrict__ in, __nv_bfloat16* __restrict__ hi,
    __nv_bfloat16* __restrict__ lo, int R, int C)
{
    __shared__ float t[32][33];
    const int c0 = blockIdx.x * 32, r0 = blockIdx.y * 32;
    const int x = threadIdx.x, y = threadIdx.y;
#pragma unroll
    for (int j = 0; j < 32; j += 8)
        t[y + j][x] = in[(size_t)(r0 + y + j) * C + c0 + x];
    __syncthreads();
#pragma unroll
    for (int j = 0; j < 32; j += 8) {
        const float v = t[x][y + j];
        __nv_bfloat16 h, l;
        split_hl(v, h, l);
        const size_t o = (size_t)(c0 + y + j) * R + r0 + x;
        hi[o] = h;
        lo[o] = l;
    }
}

// ---------------- bf16 hi/lo split GEMM (ldmatrix + mma.m16n8k16) ----------------
// C[M,N] = A[M,K] @ B[N,K]^T in ~fp32 accuracy (3-product split).
// BM=256, BN=64, BK=32; 8 warps (4m x 2n), warp tile 64x32.
#define PITCH_B 80                     // bytes per smem row (40 bf16)
#define A_PLANE (256 * PITCH_B)        // 20480 B
#define B_PLANE (64 * PITCH_B)         // 5120 B
#define HL_STAGE (2 * A_PLANE + 2 * B_PLANE)   // 51200 B
#define HL_SMEM  (2 * HL_STAGE)        // 102400 B

__global__ __launch_bounds__(256, 2) void gemm_hl(
    const __nv_bfloat16* __restrict__ Ah, const __nv_bfloat16* __restrict__ Al,
    const __nv_bfloat16* __restrict__ Bh, const __nv_bfloat16* __restrict__ Bl,
    float* __restrict__ C, int M, int N, int K)
{
    extern __shared__ __align__(128) char smx[];
    const uint32_t sbase = smem_u32(smx);
    const int tid  = threadIdx.x;
    const int warp = tid >> 5;
    const int lane = tid & 31;
    const int wm   = warp >> 1;          // 0..3 -> rows wm*64
    const int wn   = warp & 1;           // 0..1 -> cols wn*32
    const int row0 = blockIdx.y * 256;
    const int col0 = blockIdx.x * 64;

    float c[16][4];
#pragma unroll
    for (int i = 0; i < 16; i++)
#pragma unroll
        for (int j = 0; j < 4; j++) c[i][j] = 0.f;

    // ---- fill: 10 cp16 per thread per stage ----
    auto fill = [&](int stage, int k0) {
        char* st = smx + stage * HL_STAGE;
#pragma unroll
        for (int rep = 0; rep < 4; rep++) {
            const int cch = tid + rep * 256;       // 0..1023
            const int r = cch >> 2, q = cch & 3;
            const size_t src = (size_t)(row0 + r) * K + k0 + q * 8;
            cp16(st + r * PITCH_B + q * 16,            Ah + src);
            cp16(st + A_PLANE + r * PITCH_B + q * 16,  Al + src);
        }
        {
            const int r = tid >> 2, q = tid & 3;   // 64 rows x 4 chunks
            const size_t src = (size_t)(col0 + r) * K + k0 + q * 8;
            cp16(st + 2 * A_PLANE + r * PITCH_B + q * 16,            Bh + src);
            cp16(st + 2 * A_PLANE + B_PLANE + r * PITCH_B + q * 16,  Bl + src);
        }
    };

    fill(0, 0);
    CP_COMMIT();

    const int nch = K >> 5;   // K / 32
    const int rowL = (lane & 7) + (lane & 8);      // ldmatrix row-in-16
    const int kbL  = (lane >> 4) * 16;             // 8 bf16 = 16 B

    for (int ch = 0; ch < nch; ch++) {
        const int buf = ch & 1;
        if (ch + 1 < nch) {
            fill(buf ^ 1, (ch + 1) * 32);
            CP_COMMIT();
            CP_WAIT1();
        } else {
            CP_WAIT0();
        }
        __syncthreads();

        const uint32_t sAh = sbase + buf * HL_STAGE;
        const uint32_t sAl = sAh + A_PLANE;
        const uint32_t sBh = sAh + 2 * A_PLANE;
        const uint32_t sBl = sBh + B_PLANE;

#pragma unroll
        for (int kk = 0; kk < 2; kk++) {           // two k16 steps
            const int kb = kk * 32 + kbL;          // byte offset in row
            uint32_t bh[2][4], bl[2][4];
#pragma unroll
            for (int j = 0; j < 2; j++) {
                const int rB = (wn * 32 + j * 16 + rowL) * PITCH_B + kb;
                LDSM4(bh[j][0], bh[j][1], bh[j][2], bh[j][3], sBh + rB);
                LDSM4(bl[j][0], bl[j][1], bl[j][2], bl[j][3], sBl + rB);
            }
#pragma unroll
            for (int i = 0; i < 4; i++) {
                const int rA = (wm * 64 + i * 16 + rowL) * PITCH_B + kb;
                uint32_t ah0, ah1, ah2, ah3, al0, al1, al2, al3;
                LDSM4(ah0, ah1, ah2, ah3, sAh + rA);
                LDSM4(al0, al1, al2, al3, sAl + rA);
#pragma unroll
                for (int f = 0; f < 4; f++) {
                    const int j = f >> 1, h = f & 1;
                    float* acc = c[i * 4 + f];
                    mma_bf16(acc, ah0, ah1, ah2, ah3, bh[j][h], bh[j][h + 2]);
                    mma_bf16(acc, ah0, ah1, ah2, ah3, bl[j][h], bl[j][h + 2]);
                    mma_bf16(acc, al0, al1, al2, al3, bh[j][h], bh[j][h + 2]);
                }
            }
        }
        __syncthreads();
    }

    // ---- epilogue ----
    const int qr = lane >> 2, qc = 2 * (lane & 3);
#pragma unroll
    for (int i = 0; i < 4; i++) {
#pragma unroll
        for (int f = 0; f < 4; f++) {
            const int r   = row0 + wm * 64 + i * 16 + qr;
            const int col = col0 + wn * 32 + f * 8 + qc;
            *(float2*)(C + (size_t)r * N + col)       = make_float2(c[i * 4 + f][0], c[i * 4 + f][1]);
            *(float2*)(C + (size_t)(r + 8) * N + col) = make_float2(c[i * 4 + f][2], c[i * 4 + f][3]);
        }
    }
}

// ---------------- RMSNorm -> bf16 hi/lo ----------------
__global__ __launch_bounds__(256) void rmsnorm_kernel(
    const float* __restrict__ in, int ld, int off, int width,
    const float* __restrict__ gamma,
    __nv_bfloat16* __restrict__ ohi, __nv_bfloat16* __restrict__ olo)
{
    const int row = blockIdx.x;
    const float* x = in + (size_t)row * ld + off;
    float ss = 0.f;
    for (int i = threadIdx.x; i < width; i += 256) {
        float v = x[i];
        ss += v * v;
    }
#pragma unroll
    for (int o = 16; o; o >>= 1) ss += __shfl_xor_sync(0xffffffffu, ss, o);
    __shared__ float warp_s[8];
    __shared__ float s_inv;
    if ((threadIdx.x & 31) == 0) warp_s[threadIdx.x >> 5] = ss;
    __syncthreads();
    if (threadIdx.x == 0) {
        float t = 0.f;
#pragma unroll
        for (int i = 0; i < 8; i++) t += warp_s[i];
        s_inv = rsqrtf(t / (float)width + 1e-6f);
    }
    __syncthreads();
    const float inv = s_inv;
    for (int i = threadIdx.x; i < width; i += 256) {
        const float v = x[i] * inv * gamma[i];
        __nv_bfloat16 h, l;
        split_hl(v, h, l);
        ohi[(size_t)row * width + i] = h;
        olo[(size_t)row * width + i] = l;
    }
}

// ---------------- RoPE (fp32, unchanged) ----------------
__global__ __launch_bounds__(256) void rope_kernel(
    float* __restrict__ q, const float* __restrict__ qkv_a,
    float* __restrict__ kpe, const int* __restrict__ positions)
{
    const int t = blockIdx.x;
    const float pos = (float)positions[t];
    for (int i = threadIdx.x; i < NH * 32 + 32; i += 256) {
        if (i < NH * 32) {
            const int h = i >> 5, p = i & 31;
            const float inv = powf(10000.0f, -(float)p / 32.0f);
            float s, c;
            sincosf(pos * inv, &s, &c);
            float* base = q + (size_t)t * (NH * D_QK) + h * D_QK + D_NOPE;
            const float x1 = base[2 * p], x2 = base[2 * p + 1];
            base[2 * p]     = x1 * c - x2 * s;
            base[2 * p + 1] = x1 * s + x2 * c;
        } else {
            const int p = i - NH * 32;
            const float inv = powf(10000.0f, -(float)p / 32.0f);
            float s, c;
            sincosf(pos * inv, &s, &c);
            const float* src = qkv_a + (size_t)t * QKV_A_N + (Q_LORA + KV_LORA);
            const float x1 = src[2 * p], x2 = src[2 * p + 1];
            kpe[(size_t)t * D_ROPE + 2 * p]     = x1 * c - x2 * s;
            kpe[(size_t)t * D_ROPE + 2 * p + 1] = x1 * s + x2 * c;
        }
    }
}

// ---------------- tf32 tensor-core causal flash attention (R4, epilogue -> hi/lo) ----------------
__device__ __forceinline__ unsigned int f2tf(float x) {
    unsigned int u;
    asm("cvt.rna.tf32.f32 %0, %1;" : "=r"(u) : "f"(x));
    return u;
}
__device__ __forceinline__ void mma_tf32(float* c,
    unsigned int a0, unsigned int a1, unsigned int a2, unsigned int a3,
    unsigned int b0, unsigned int b1)
{
    asm volatile(
        "mma.sync.aligned.m16n8k8.row.col.f32.tf32.tf32.f32 "
        "{%0,%1,%2,%3},{%4,%5,%6,%7},{%8,%9},{%0,%1,%2,%3};"
        : "+f"(c[0]), "+f"(c[1]), "+f"(c[2]), "+f"(c[3])
        : "r"(a0), "r"(a1), "r"(a2), "r"(a3), "r"(b0), "r"(b1));
}

#define AT_LDQ 196
#define AT_LDV 136
#define AT_LDP 68
#define AT_SMEM_FLOATS (64*AT_LDQ + 64*AT_LDQ + 64*AT_LDV + 64*AT_LDP + 128 + 128 + 64 + 64 + 64)

__global__ __launch_bounds__(256, 1) void attn_tc_kernel(
    const float* __restrict__ q, const float* __restrict__ kv,
    const float* __restrict__ kpe,
    uint32_t* __restrict__ ohi, uint32_t* __restrict__ olo)
{
    extern __shared__ float sm[];
    float* sQ     = sm;
    float* sK     = sQ + 64 * AT_LDQ;
    float* sV     = sK + 64 * AT_LDQ;
    float* sP     = sV + 64 * AT_LDV;
    float* sWmax  = sP + 64 * AT_LDP;
    float* sWsum  = sWmax + 128;
    float* sM     = sWsum + 128;
    float* sL     = sM + 64;
    float* sScale = sL + 64;

    const int h   = blockIdx.y;
    const int qt  = blockIdx.x;
    const int t0  = qt * 64;
    const int tid = threadIdx.x;
    const int w   = tid >> 5;
    const int lane = tid & 31;
    const int g   = lane >> 2;
    const int t   = lane & 3;
    const int mrow = (w & 3) * 16;
    const int nhalf = w >> 2;
    const int r0 = mrow + g, r1 = r0 + 8;

    for (int i = tid; i < 64 * 192; i += 256) {
        const int r = i / 192, d = i - r * 192;
        sQ[r * AT_LDQ + d] = q[(size_t)(t0 + r) * (NH * D_QK) + h * D_QK + d];
    }
    if (tid < 64) { sM[tid] = -1e30f; sL[tid] = 0.f; }

    float o[8][4];
#pragma unroll
    for (int i = 0; i < 8; i++)
#pragma unroll
        for (int j = 0; j < 4; j++) o[i][j] = 0.f;

    for (int kt = 0; kt <= qt; kt++) {
        const int k0 = kt * 64;
        __syncthreads();
        for (int i = tid; i < 64 * 192; i += 256) {
            const int r = i / 192, d = i - r * 192;
            sK[r * AT_LDQ + d] = (d < 128)
                ? kv[(size_t)(k0 + r) * (NH * 256) + h * 256 + d]
                : kpe[(size_t)(k0 + r) * D_ROPE + (d - 128)];
        }
        for (int i = tid; i < 64 * 128; i += 256) {
            const int r = i >> 7, d = i & 127;
            sV[r * AT_LDV + d] = kv[(size_t)(k0 + r) * (NH * 256) + h * 256 + 128 + d];
        }
        __syncthreads();

        float s[4][4];
#pragma unroll
        for (int nt = 0; nt < 4; nt++)
#pragma unroll
            for (int j = 0; j < 4; j++) s[nt][j] = 0.f;

        const float* qb = sQ + r0 * AT_LDQ + t;
#pragma unroll 4
        for (int kk = 0; kk < 192; kk += 8) {
            const unsigned int a0 = f2tf(qb[kk]);
            const unsigned int a1 = f2tf(qb[8 * AT_LDQ + kk]);
            const unsigned int a2 = f2tf(qb[kk + 4]);
            const unsigned int a3 = f2tf(qb[8 * AT_LDQ + kk + 4]);
#pragma unroll
            for (int nt = 0; nt < 4; nt++) {
                const int key = nhalf * 32 + nt * 8 + g;
                const unsigned int b0 = f2tf(sK[key * AT_LDQ + kk + t]);
                const unsigned int b1 = f2tf(sK[key * AT_LDQ + kk + t + 4]);
                mma_tf32(s[nt], a0, a1, a2, a3, b0, b1);
            }
        }

        const int rg0 = t0 + r0, rg1 = t0 + r1;
#pragma unroll
        for (int nt = 0; nt < 4; nt++) {
            const int cg = k0 + nhalf * 32 + nt * 8 + 2 * t;
            s[nt][0] = (rg0 >= cg)     ? s[nt][0] * SCALING : -1e30f;
            s[nt][1] = (rg0 >= cg + 1) ? s[nt][1] * SCALING : -1e30f;
            s[nt][2] = (rg1 >= cg)     ? s[nt][2] * SCALING : -1e30f;
            s[nt][3] = (rg1 >= cg + 1) ? s[nt][3] * SCALING : -1e30f;
        }

        float mx0 = -1e30f, mx1 = -1e30f;
#pragma unroll
        for (int nt = 0; nt < 4; nt++) {
            mx0 = fmaxf(mx0, fmaxf(s[nt][0], s[nt][1]));
            mx1 = fmaxf(mx1, fmaxf(s[nt][2], s[nt][3]));
        }
        mx0 = fmaxf(mx0, __shfl_xor_sync(0xffffffffu, mx0, 1));
        mx0 = fmaxf(mx0, __shfl_xor_sync(0xffffffffu, mx0, 2));
        mx1 = fmaxf(mx1, __shfl_xor_sync(0xffffffffu, mx1, 1));
        mx1 = fmaxf(mx1, __shfl_xor_sync(0xffffffffu, mx1, 2));
        if (t == 0) { sWmax[nhalf * 64 + r0] = mx0; sWmax[nhalf * 64 + r1] = mx1; }
        __syncthreads();

        const float mn0 = fmaxf(sM[r0], fmaxf(sWmax[r0], sWmax[64 + r0]));
        const float mn1 = fmaxf(sM[r1], fmaxf(sWmax[r1], sWmax[64 + r1]));

        float sum0 = 0.f, sum1 = 0.f;
#pragma unroll
        for (int nt = 0; nt < 4; nt++) {
            s[nt][0] = __expf(s[nt][0] - mn0);
            s[nt][1] = __expf(s[nt][1] - mn0);
            s[nt][2] = __expf(s[nt][2] - mn1);
            s[nt][3] = __expf(s[nt][3] - mn1);
            sum0 += s[nt][0] + s[nt][1];
            sum1 += s[nt][2] + s[nt][3];
            const int coll = nhalf * 32 + nt * 8 + 2 * t;
            *(float2*)(sP + r0 * AT_LDP + coll) = make_float2(s[nt][0], s[nt][1]);
            *(float2*)(sP + r1 * AT_LDP + coll) = make_float2(s[nt][2], s[nt][3]);
        }
        sum0 += __shfl_xor_sync(0xffffffffu, sum0, 1);
        sum0 += __shfl_xor_sync(0xffffffffu, sum0, 2);
        sum1 += __shfl_xor_sync(0xffffffffu, sum1, 1);
        sum1 += __shfl_xor_sync(0xffffffffu, sum1, 2);
        if (t == 0) { sWsum[nhalf * 64 + r0] = sum0; sWsum[nhalf * 64 + r1] = sum1; }
        __syncthreads();

        if (tid < 64) {
            const float mo = sM[tid];
            const float mn = fmaxf(mo, fmaxf(sWmax[tid], sWmax[64 + tid]));
            const float sc = __expf(mo - mn);
            sM[tid] = mn;
            sL[tid] = sL[tid] * sc + sWsum[tid] + sWsum[64 + tid];
            sScale[tid] = sc;
        }
        __syncthreads();

        const float sc0 = sScale[r0], sc1 = sScale[r1];
#pragma unroll
        for (int nt = 0; nt < 8; nt++) {
            o[nt][0] *= sc0; o[nt][1] *= sc0;
            o[nt][2] *= sc1; o[nt][3] *= sc1;
        }

        const float* pb = sP + r0 * AT_LDP + t;
#pragma unroll 2
        for (int kk = 0; kk < 64; kk += 8) {
            const unsigned int a0 = f2tf(pb[kk]);
            const unsigned int a1 = f2tf(pb[8 * AT_LDP + kk]);
            const unsigned int a2 = f2tf(pb[kk + 4]);
            const unsigned int a3 = f2tf(pb[8 * AT_LDP + kk + 4]);
#pragma unroll
            for (int nt = 0; nt < 8; nt++) {
                const int nc = nhalf * 64 + nt * 8 + g;
                const unsigned int b0 = f2tf(sV[(kk + t) * AT_LDV + nc]);
                const unsigned int b1 = f2tf(sV[(kk + t + 4) * AT_LDV + nc]);
                mma_tf32(o[nt], a0, a1, a2, a3, b0, b1);
            }
        }
    }

    const float il0 = 1.f / sL[r0];
    const float il1 = 1.f / sL[r1];
#pragma unroll
    for (int nt = 0; nt < 8; nt++) {
        const int col = h * D_V + nhalf * 64 + nt * 8 + 2 * t;
        const float v00 = o[nt][0] * il0, v01 = o[nt][1] * il0;
        const float v10 = o[nt][2] * il1, v11 = o[nt][3] * il1;
        __nv_bfloat16 h0, l0, h1, l1;
        split_hl(v00, h0, l0); split_hl(v01, h1, l1);
        ohi[((size_t)(t0 + r0) * (NH * D_V) + col) >> 1] =
            (uint32_t)__bfloat16_as_ushort(h0) | ((uint32_t)__bfloat16_as_ushort(h1) << 16);
        olo[((size_t)(t0 + r0) * (NH * D_V) + col) >> 1] =
            (uint32_t)__bfloat16_as_ushort(l0) | ((uint32_t)__bfloat16_as_ushort(l1) << 16);
        split_hl(v10, h0, l0); split_hl(v11, h1, l1);
        ohi[((size_t)(t0 + r1) * (NH * D_V) + col) >> 1] =
            (uint32_t)__bfloat16_as_ushort(h0) | ((uint32_t)__bfloat16_as_ushort(h1) << 16);
        olo[((size_t)(t0 + r1) * (NH * D_V) + col) >> 1] =
            (uint32_t)__bfloat16_as_ushort(l0) | ((uint32_t)__bfloat16_as_ushort(l1) << 16);
    }
}

// ---------------- launch ----------------
extern "C" void kernel_launch(void* const* d_in, const int* in_sizes, int n_in,
                              void* d_out, int out_size)
{
    const float* hidden    = (const float*)d_in[0];
    const int*   positions = (const int*)  d_in[1];
    const float* w_qkv_a   = (const float*)d_in[2];
    const float* gamma_q   = (const float*)d_in[3];
    const float* w_q_b     = (const float*)d_in[4];
    const float* gamma_kv  = (const float*)d_in[5];
    const float* w_kv_b    = (const float*)d_in[6];
    const float* w_o       = (const float*)d_in[7];
    float* out = (float*)d_out;

    float *qkv_a, *qbuf, *kvbuf, *kpe;
    __nv_bfloat16 *hid_h, *hid_l, *qn_h, *qn_l, *kvn_h, *kvn_l, *at_h, *at_l;
    __nv_bfloat16 *wa_h, *wa_l, *wqb_h, *wqb_l, *wkvb_h, *wkvb_l, *wo_h, *wo_l;
    cudaGetSymbolAddress((void**)&qkv_a, g_qkv_a);
    cudaGetSymbolAddress((void**)&qbuf,  g_qbuf);
    cudaGetSymbolAddress((void**)&kvbuf, g_kvbuf);
    cudaGetSymbolAddress((void**)&kpe,   g_kpe);
    cudaGetSymbolAddress((void**)&hid_h, g_hid_hi);  cudaGetSymbolAddress((void**)&hid_l, g_hid_lo);
    cudaGetSymbolAddress((void**)&qn_h,  g_qn_hi);   cudaGetSymbolAddress((void**)&qn_l,  g_qn_lo);
    cudaGetSymbolAddress((void**)&kvn_h, g_kvn_hi);  cudaGetSymbolAddress((void**)&kvn_l, g_kvn_lo);
    cudaGetSymbolAddress((void**)&at_h,  g_attn_hi); cudaGetSymbolAddress((void**)&at_l,  g_attn_lo);
    cudaGetSymbolAddress((void**)&wa_h,  g_wa_hi);   cudaGetSymbolAddress((void**)&wa_l,  g_wa_lo);
    cudaGetSymbolAddress((void**)&wqb_h, g_wqb_hi);  cudaGetSymbolAddress((void**)&wqb_l, g_wqb_lo);
    cudaGetSymbolAddress((void**)&wkvb_h,g_wkvb_hi); cudaGetSymbolAddress((void**)&wkvb_l,g_wkvb_lo);
    cudaGetSymbolAddress((void**)&wo_h,  g_wo_hi);   cudaGetSymbolAddress((void**)&wo_l,  g_wo_lo);

    cudaFuncSetAttribute(gemm_hl, cudaFuncAttributeMaxDynamicSharedMemorySize, HL_SMEM);
    const int attn_smem = AT_SMEM_FLOATS * (int)sizeof(float);
    cudaFuncSetAttribute(attn_tc_kernel, cudaFuncAttributeMaxDynamicSharedMemorySize, attn_smem);

    // 0) one-time conversions
    convert_hl_kernel<<<1184, 256>>>((const float2*)hidden,
        (uint32_t*)hid_h, (uint32_t*)hid_l, T_TOK * HID / 2);
    transpose_cvt_kernel<<<dim3(QKV_A_N / 32, HID / 32),      dim3(32, 8)>>>(w_qkv_a, wa_h,   wa_l,   HID,      QKV_A_N);
    transpose_cvt_kernel<<<dim3((NH*D_QK) / 32, Q_LORA / 32), dim3(32, 8)>>>(w_q_b,   wqb_h,  wqb_l,  Q_LORA,   NH * D_QK);
    transpose_cvt_kernel<<<dim3((NH*256) / 32, KV_LORA / 32), dim3(32, 8)>>>(w_kv_b,  wkvb_h, wkvb_l, KV_LORA,  NH * 256);
    transpose_cvt_kernel<<<dim3(HID / 32, (NH*D_V) / 32),     dim3(32, 8)>>>(w_o,     wo_h,   wo_l,   NH * D_V, HID);

    // 1) qkv_a = hidden @ w_qkv_a
    gemm_hl<<<dim3(QKV_A_N / 64, T_TOK / 256), 256, HL_SMEM>>>(
        hid_h, hid_l, wa_h, wa_l, qkv_a, T_TOK, QKV_A_N, HID);

    // 2) RMSNorm -> hi/lo
    rmsnorm_kernel<<<T_TOK, 256>>>(qkv_a, QKV_A_N, 0,      Q_LORA,  gamma_q,  qn_h,  qn_l);
    rmsnorm_kernel<<<T_TOK, 256>>>(qkv_a, QKV_A_N, Q_LORA, KV_LORA, gamma_kv, kvn_h, kvn_l);

    // 3) q = qn @ w_q_b
    gemm_hl<<<dim3((NH * D_QK) / 64, T_TOK / 256), 256, HL_SMEM>>>(
        qn_h, qn_l, wqb_h, wqb_l, qbuf, T_TOK, NH * D_QK, Q_LORA);

    // 4) kv = kvn @ w_kv_b
    gemm_hl<<<dim3((NH * 256) / 64, T_TOK / 256), 256, HL_SMEM>>>(
        kvn_h, kvn_l, wkvb_h, wkvb_l, kvbuf, T_TOK, NH * 256, KV_LORA);

    // 5) RoPE
    rope_kernel<<<T_TOK, 256>>>(qbuf, qkv_a, kpe, positions);

    // 6) attention -> hi/lo planes
    attn_tc_kernel<<<dim3(T_TOK / 64, NH), 256, attn_smem>>>(
        qbuf, kvbuf, kpe, (uint32_t*)at_h, (uint32_t*)at_l);

    // 7) out = attn @ w_o
    gemm_hl<<<dim3(HID / 64, T_TOK / 256), 256, HL_SMEM>>>(
        at_h, at_l, wo_h, wo_l, out, T_TOK, HID, NH * D_V);
}

// round 8
// speedup vs baseline: 1.6022x; 1.3744x over previous
#include <cuda_runtime.h>
#include <cuda_bf16.h>
#include <math.h>
#include <stdint.h>

// ---------------- problem constants ----------------
#define T_TOK   2048
#define HID     2048
#define NH      16
#define D_NOPE  128
#define D_ROPE  64
#define D_QK    192
#define D_V     128
#define Q_LORA  1536
#define KV_LORA 512
#define QKV_A_N 2112
#define SCALING 0.07216878364870322f   // 192^-0.5

// ---------------- scratch ----------------
__device__ __align__(128) float g_qkv_a [T_TOK * QKV_A_N];
__device__ __align__(128) float g_qbuf  [T_TOK * NH * D_QK];
__device__ __align__(128) float g_kvbuf [T_TOK * NH * 256];
__device__ __align__(128) float g_kpe   [T_TOK * D_ROPE];
// bf16 hi/lo planes
__device__ __align__(128) __nv_bfloat16 g_hid_hi [T_TOK * HID];
__device__ __align__(128) __nv_bfloat16 g_hid_lo [T_TOK * HID];
__device__ __align__(128) __nv_bfloat16 g_qn_hi  [T_TOK * Q_LORA];
__device__ __align__(128) __nv_bfloat16 g_qn_lo  [T_TOK * Q_LORA];
__device__ __align__(128) __nv_bfloat16 g_kvn_hi [T_TOK * KV_LORA];
__device__ __align__(128) __nv_bfloat16 g_kvn_lo [T_TOK * KV_LORA];
__device__ __align__(128) __nv_bfloat16 g_attn_hi[T_TOK * NH * D_V];
__device__ __align__(128) __nv_bfloat16 g_attn_lo[T_TOK * NH * D_V];
__device__ __align__(128) __nv_bfloat16 g_wa_hi  [QKV_A_N * HID];
__device__ __align__(128) __nv_bfloat16 g_wa_lo  [QKV_A_N * HID];
__device__ __align__(128) __nv_bfloat16 g_wqb_hi [NH * D_QK * Q_LORA];
__device__ __align__(128) __nv_bfloat16 g_wqb_lo [NH * D_QK * Q_LORA];
__device__ __align__(128) __nv_bfloat16 g_wkvb_hi[NH * 256 * KV_LORA];
__device__ __align__(128) __nv_bfloat16 g_wkvb_lo[NH * 256 * KV_LORA];
__device__ __align__(128) __nv_bfloat16 g_wo_hi  [HID * NH * D_V];
__device__ __align__(128) __nv_bfloat16 g_wo_lo  [HID * NH * D_V];
// attention operand planes
__device__ __align__(128) __nv_bfloat16 g_q_hi  [T_TOK * NH * D_QK];
__device__ __align__(128) __nv_bfloat16 g_q_lo  [T_TOK * NH * D_QK];
__device__ __align__(128) __nv_bfloat16 g_k_hi  [T_TOK * NH * D_QK];
__device__ __align__(128) __nv_bfloat16 g_k_lo  [T_TOK * NH * D_QK];
__device__ __align__(128) __nv_bfloat16 g_vt_hi [NH * D_V * T_TOK];
__device__ __align__(128) __nv_bfloat16 g_vt_lo [NH * D_V * T_TOK];

// ---------------- helpers ----------------
__device__ __forceinline__ void cp16(void* s, const void* g) {
    unsigned int sa = (unsigned int)__cvta_generic_to_shared(s);
    asm volatile("cp.async.cg.shared.global [%0], [%1], 16;" :: "r"(sa), "l"(g));
}
#define CP_COMMIT() asm volatile("cp.async.commit_group;")
#define CP_WAIT1()  asm volatile("cp.async.wait_group 1;")
#define CP_WAIT0()  asm volatile("cp.async.wait_group 0;")

__device__ __forceinline__ uint32_t smem_u32(const void* p) {
    return (uint32_t)__cvta_generic_to_shared(p);
}
#define LDSM4(r0, r1, r2, r3, a) \
    asm volatile("ldmatrix.sync.aligned.m8n8.x4.shared.b16 {%0,%1,%2,%3}, [%4];" \
        : "=r"(r0), "=r"(r1), "=r"(r2), "=r"(r3) : "r"(a))

__device__ __forceinline__ void mma_bf16(float* c,
    uint32_t a0, uint32_t a1, uint32_t a2, uint32_t a3, uint32_t b0, uint32_t b1)
{
    asm volatile(
        "mma.sync.aligned.m16n8k16.row.col.f32.bf16.bf16.f32 "
        "{%0,%1,%2,%3},{%4,%5,%6,%7},{%8,%9},{%0,%1,%2,%3};"
        : "+f"(c[0]), "+f"(c[1]), "+f"(c[2]), "+f"(c[3])
        : "r"(a0), "r"(a1), "r"(a2), "r"(a3), "r"(b0), "r"(b1));
}

__device__ __forceinline__ void split_hl(float v, __nv_bfloat16& h, __nv_bfloat16& l) {
    h = __float2bfloat16(v);
    l = __float2bfloat16(v - __bfloat162float(h));
}
__device__ __forceinline__ uint32_t pack2(__nv_bfloat16 a, __nv_bfloat16 b) {
    return (uint32_t)__bfloat16_as_ushort(a) | ((uint32_t)__bfloat16_as_ushort(b) << 16);
}

// ---------------- converters ----------------
__global__ __launch_bounds__(256) void convert_hl_kernel(
    const float2* __restrict__ src, uint32_t* __restrict__ hi,
    uint32_t* __restrict__ lo, int n2)
{
    int i = blockIdx.x * 256 + threadIdx.x;
    const int stride = gridDim.x * 256;
    for (; i < n2; i += stride) {
        const float2 v = src[i];
        __nv_bfloat16 h0, l0, h1, l1;
        split_hl(v.x, h0, l0);
        split_hl(v.y, h1, l1);
        hi[i] = pack2(h0, h1);
        lo[i] = pack2(l0, l1);
    }
}

// in fp32 [R][C] -> out hi/lo bf16 [C][R]
__global__ __launch_bounds__(256) void transpose_cvt_kernel(
    const float* __restrict__ in, __nv_bfloat16* __restrict__ hi,
    __nv_bfloat16* __restrict__ lo, int R, int C)
{
    __shared__ float t[32][33];
    const int c0 = blockIdx.x * 32, r0 = blockIdx.y * 32;
    const int x = threadIdx.x, y = threadIdx.y;
#pragma unroll
    for (int j = 0; j < 32; j += 8)
        t[y + j][x] = in[(size_t)(r0 + y + j) * C + c0 + x];
    __syncthreads();
#pragma unroll
    for (int j = 0; j < 32; j += 8) {
        const float v = t[x][y + j];
        __nv_bfloat16 h, l;
        split_hl(v, h, l);
        const size_t o = (size_t)(c0 + y + j) * R + r0 + x;
        hi[o] = h;
        lo[o] = l;
    }
}

// build K planes: k[t][h*192+d] = d<128 ? kv[t][h*256+d] : kpe[t][d-128]
__global__ __launch_bounds__(256) void build_k_kernel(
    const float* __restrict__ kvbuf, const float* __restrict__ kpe,
    __nv_bfloat16* __restrict__ kh, __nv_bfloat16* __restrict__ kl)
{
    const int t = blockIdx.x;
    for (int i = threadIdx.x; i < NH * D_QK; i += 256) {
        const int h = i / D_QK, d = i - h * D_QK;
        const float v = (d < 128)
            ? kvbuf[(size_t)t * (NH * 256) + h * 256 + d]
            : kpe[(size_t)t * D_ROPE + (d - 128)];
        __nv_bfloat16 hh, ll;
        split_hl(v, hh, ll);
        kh[(size_t)t * (NH * D_QK) + i] = hh;
        kl[(size_t)t * (NH * D_QK) + i] = ll;
    }
}

// build VT planes: vt[h][d][t] = kvbuf[t][h*256+128+d]
__global__ __launch_bounds__(256) void build_vt_kernel(
    const float* __restrict__ kvbuf,
    __nv_bfloat16* __restrict__ vth, __nv_bfloat16* __restrict__ vtl)
{
    __shared__ float tile[32][33];
    const int h = blockIdx.z;
    const int d0 = blockIdx.y * 32;
    const int t0 = blockIdx.x * 32;
    const int x = threadIdx.x, y = threadIdx.y;
#pragma unroll
    for (int j = 0; j < 32; j += 8)
        tile[y + j][x] = kvbuf[(size_t)(t0 + y + j) * (NH * 256) + h * 256 + 128 + d0 + x];
    __syncthreads();
#pragma unroll
    for (int j = 0; j < 32; j += 8) {
        const float v = tile[x][y + j];
        __nv_bfloat16 hh, ll;
        split_hl(v, hh, ll);
        const size_t o = ((size_t)h * D_V + d0 + y + j) * T_TOK + t0 + x;
        vth[o] = hh;
        vtl[o] = ll;
    }
}

// ---------------- bf16 hi/lo split GEMM (unchanged from R7) ----------------
#define PITCH_B 80
#define A_PLANE (256 * PITCH_B)
#define B_PLANE (64 * PITCH_B)
#define HL_STAGE (2 * A_PLANE + 2 * B_PLANE)
#define HL_SMEM  (2 * HL_STAGE)

__global__ __launch_bounds__(256, 2) void gemm_hl(
    const __nv_bfloat16* __restrict__ Ah, const __nv_bfloat16* __restrict__ Al,
    const __nv_bfloat16* __restrict__ Bh, const __nv_bfloat16* __restrict__ Bl,
    float* __restrict__ C, int M, int N, int K)
{
    extern __shared__ __align__(128) char smx[];
    const uint32_t sbase = smem_u32(smx);
    const int tid  = threadIdx.x;
    const int warp = tid >> 5;
    const int lane = tid & 31;
    const int wm   = warp >> 1;
    const int wn   = warp & 1;
    const int row0 = blockIdx.y * 256;
    const int col0 = blockIdx.x * 64;

    float c[16][4];
#pragma unroll
    for (int i = 0; i < 16; i++)
#pragma unroll
        for (int j = 0; j < 4; j++) c[i][j] = 0.f;

    auto fill = [&](int stage, int k0) {
        char* st = smx + stage * HL_STAGE;
#pragma unroll
        for (int rep = 0; rep < 4; rep++) {
            const int cch = tid + rep * 256;
            const int r = cch >> 2, q = cch & 3;
            const size_t src = (size_t)(row0 + r) * K + k0 + q * 8;
            cp16(st + r * PITCH_B + q * 16,            Ah + src);
            cp16(st + A_PLANE + r * PITCH_B + q * 16,  Al + src);
        }
        {
            const int r = tid >> 2, q = tid & 3;
            const size_t src = (size_t)(col0 + r) * K + k0 + q * 8;
            cp16(st + 2 * A_PLANE + r * PITCH_B + q * 16,            Bh + src);
            cp16(st + 2 * A_PLANE + B_PLANE + r * PITCH_B + q * 16,  Bl + src);
        }
    };

    fill(0, 0);
    CP_COMMIT();

    const int nch = K >> 5;
    const int rowL = (lane & 7) + (lane & 8);
    const int kbL  = (lane >> 4) * 16;

    for (int ch = 0; ch < nch; ch++) {
        const int buf = ch & 1;
        if (ch + 1 < nch) {
            fill(buf ^ 1, (ch + 1) * 32);
            CP_COMMIT();
            CP_WAIT1();
        } else {
            CP_WAIT0();
        }
        __syncthreads();

        const uint32_t sAh = sbase + buf * HL_STAGE;
        const uint32_t sAl = sAh + A_PLANE;
        const uint32_t sBh = sAh + 2 * A_PLANE;
        const uint32_t sBl = sBh + B_PLANE;

#pragma unroll
        for (int kk = 0; kk < 2; kk++) {
            const int kb = kk * 32 + kbL;
            uint32_t bh[2][4], bl[2][4];
#pragma unroll
            for (int j = 0; j < 2; j++) {
                const int rB = (wn * 32 + j * 16 + rowL) * PITCH_B + kb;
                LDSM4(bh[j][0], bh[j][1], bh[j][2], bh[j][3], sBh + rB);
                LDSM4(bl[j][0], bl[j][1], bl[j][2], bl[j][3], sBl + rB);
            }
#pragma unroll
            for (int i = 0; i < 4; i++) {
                const int rA = (wm * 64 + i * 16 + rowL) * PITCH_B + kb;
                uint32_t ah0, ah1, ah2, ah3, al0, al1, al2, al3;
                LDSM4(ah0, ah1, ah2, ah3, sAh + rA);
                LDSM4(al0, al1, al2, al3, sAl + rA);
#pragma unroll
                for (int f = 0; f < 4; f++) {
                    const int j = f >> 1, h = f & 1;
                    float* acc = c[i * 4 + f];
                    mma_bf16(acc, ah0, ah1, ah2, ah3, bh[j][h], bh[j][h + 2]);
                    mma_bf16(acc, ah0, ah1, ah2, ah3, bl[j][h], bl[j][h + 2]);
                    mma_bf16(acc, al0, al1, al2, al3, bh[j][h], bh[j][h + 2]);
                }
            }
        }
        __syncthreads();
    }

    const int qr = lane >> 2, qc = 2 * (lane & 3);
#pragma unroll
    for (int i = 0; i < 4; i++) {
#pragma unroll
        for (int f = 0; f < 4; f++) {
            const int r   = row0 + wm * 64 + i * 16 + qr;
            const int col = col0 + wn * 32 + f * 8 + qc;
            *(float2*)(C + (size_t)r * N + col)       = make_float2(c[i * 4 + f][0], c[i * 4 + f][1]);
            *(float2*)(C + (size_t)(r + 8) * N + col) = make_float2(c[i * 4 + f][2], c[i * 4 + f][3]);
        }
    }
}

// ---------------- RMSNorm -> bf16 hi/lo ----------------
__global__ __launch_bounds__(256) void rmsnorm_kernel(
    const float* __restrict__ in, int ld, int off, int width,
    const float* __restrict__ gamma,
    __nv_bfloat16* __restrict__ ohi, __nv_bfloat16* __restrict__ olo)
{
    const int row = blockIdx.x;
    const float* x = in + (size_t)row * ld + off;
    float ss = 0.f;
    for (int i = threadIdx.x; i < width; i += 256) {
        float v = x[i];
        ss += v * v;
    }
#pragma unroll
    for (int o = 16; o; o >>= 1) ss += __shfl_xor_sync(0xffffffffu, ss, o);
    __shared__ float warp_s[8];
    __shared__ float s_inv;
    if ((threadIdx.x & 31) == 0) warp_s[threadIdx.x >> 5] = ss;
    __syncthreads();
    if (threadIdx.x == 0) {
        float t = 0.f;
#pragma unroll
        for (int i = 0; i < 8; i++) t += warp_s[i];
        s_inv = rsqrtf(t / (float)width + 1e-6f);
    }
    __syncthreads();
    const float inv = s_inv;
    for (int i = threadIdx.x; i < width; i += 256) {
        const float v = x[i] * inv * gamma[i];
        __nv_bfloat16 h, l;
        split_hl(v, h, l);
        ohi[(size_t)row * width + i] = h;
        olo[(size_t)row * width + i] = l;
    }
}

// ---------------- RoPE (fp32) ----------------
__global__ __launch_bounds__(256) void rope_kernel(
    float* __restrict__ q, const float* __restrict__ qkv_a,
    float* __restrict__ kpe, const int* __restrict__ positions)
{
    const int t = blockIdx.x;
    const float pos = (float)positions[t];
    for (int i = threadIdx.x; i < NH * 32 + 32; i += 256) {
        if (i < NH * 32) {
            const int h = i >> 5, p = i & 31;
            const float inv = powf(10000.0f, -(float)p / 32.0f);
            float s, c;
            sincosf(pos * inv, &s, &c);
            float* base = q + (size_t)t * (NH * D_QK) + h * D_QK + D_NOPE;
            const float x1 = base[2 * p], x2 = base[2 * p + 1];
            base[2 * p]     = x1 * c - x2 * s;
            base[2 * p + 1] = x1 * s + x2 * c;
        } else {
            const int p = i - NH * 32;
            const float inv = powf(10000.0f, -(float)p / 32.0f);
            float s, c;
            sincosf(pos * inv, &s, &c);
            const float* src = qkv_a + (size_t)t * QKV_A_N + (Q_LORA + KV_LORA);
            const float x1 = src[2 * p], x2 = src[2 * p + 1];
            kpe[(size_t)t * D_ROPE + 2 * p]     = x1 * c - x2 * s;
            kpe[(size_t)t * D_ROPE + 2 * p + 1] = x1 * s + x2 * c;
        }
    }
}

// ---------------- bf16 hi/lo causal flash attention ----------------
// Q/K rows 192 bf16 (384 B used), pitch 400 B; VT/P rows 64 bf16 (128 B), pitch 144 B.
#define SQH 0
#define SQL 25600
#define SKH 51200
#define SKL 76800
#define SVH 102400
#define SVL 120832
#define SPH 139264
#define SPL 148480
#define SSTAT 157696
#define ATT_SMEM (SSTAT + 1792)

__global__ __launch_bounds__(256, 1) void attn_hl_kernel(
    const __nv_bfloat16* __restrict__ qh, const __nv_bfloat16* __restrict__ ql,
    const __nv_bfloat16* __restrict__ kh, const __nv_bfloat16* __restrict__ kl,
    const __nv_bfloat16* __restrict__ vth, const __nv_bfloat16* __restrict__ vtl,
    uint32_t* __restrict__ ohi, uint32_t* __restrict__ olo)
{
    extern __shared__ __align__(128) char sma[];
    const uint32_t sb = smem_u32(sma);
    float* sWmax  = (float*)(sma + SSTAT);   // [2][64]
    float* sWsum  = sWmax + 128;             // [2][64]
    float* sM     = sWsum + 128;             // 64
    float* sL     = sM + 64;                 // 64
    float* sScale = sL + 64;                 // 64

    const int h    = blockIdx.y;
    const int qt   = blockIdx.x;
    const int t0   = qt * 64;
    const int tid  = threadIdx.x;
    const int w    = tid >> 5;
    const int lane = tid & 31;
    const int g    = lane >> 2;
    const int t    = lane & 3;
    const int mrow = (w & 3) * 16;
    const int nhalf = w >> 2;
    const int r0 = mrow + g, r1 = r0 + 8;

    // Q tile (once), via cp.async
    for (int i = tid; i < 1536; i += 256) {
        const int r = i / 24, c = i - r * 24;
        const size_t src = (size_t)(t0 + r) * (NH * D_QK) + h * D_QK + c * 8;
        cp16(sma + SQH + r * 400 + c * 16, qh + src);
        cp16(sma + SQL + r * 400 + c * 16, ql + src);
    }
    CP_COMMIT();
    if (tid < 64) { sM[tid] = -1e30f; sL[tid] = 0.f; }

    float o[8][4];
#pragma unroll
    for (int i = 0; i < 8; i++)
#pragma unroll
        for (int j = 0; j < 4; j++) o[i][j] = 0.f;

    const int rowL = (lane & 7) + (lane & 8);
    const int kbL  = (lane >> 4) * 16;

    for (int kt = 0; kt <= qt; kt++) {
        const int k0 = kt * 64;
        __syncthreads();   // previous iteration consumers done
        for (int i = tid; i < 1536; i += 256) {
            const int r = i / 24, c = i - r * 24;
            const size_t src = (size_t)(k0 + r) * (NH * D_QK) + h * D_QK + c * 8;
            cp16(sma + SKH + r * 400 + c * 16, kh + src);
            cp16(sma + SKL + r * 400 + c * 16, kl + src);
        }
        for (int i = tid; i < 1024; i += 256) {
            const int r = i >> 3, c = i & 7;
            const size_t src = ((size_t)h * D_V + r) * T_TOK + k0 + c * 8;
            cp16(sma + SVH + r * 144 + c * 16, vth + src);
            cp16(sma + SVL + r * 144 + c * 16, vtl + src);
        }
        CP_COMMIT();
        CP_WAIT0();
        __syncthreads();

        // ---- S = Q @ K^T (hi/lo 3-product) ----
        float s[4][4];
#pragma unroll
        for (int nt = 0; nt < 4; nt++)
#pragma unroll
            for (int j = 0; j < 4; j++) s[nt][j] = 0.f;

#pragma unroll 3
        for (int ks = 0; ks < 12; ks++) {
            const int kb = ks * 32 + kbL;
            uint32_t ah0, ah1, ah2, ah3, al0, al1, al2, al3;
            const int rA = (mrow + rowL) * 400 + kb;
            LDSM4(ah0, ah1, ah2, ah3, sb + SQH + rA);
            LDSM4(al0, al1, al2, al3, sb + SQL + rA);
            uint32_t bh[2][4], bl[2][4];
#pragma unroll
            for (int j = 0; j < 2; j++) {
                const int rB = (nhalf * 32 + j * 16 + rowL) * 400 + kb;
                LDSM4(bh[j][0], bh[j][1], bh[j][2], bh[j][3], sb + SKH + rB);
                LDSM4(bl[j][0], bl[j][1], bl[j][2], bl[j][3], sb + SKL + rB);
            }
#pragma unroll
            for (int nt = 0; nt < 4; nt++) {
                const int j = nt >> 1, hh = nt & 1;
                mma_bf16(s[nt], ah0, ah1, ah2, ah3, bh[j][hh], bh[j][hh + 2]);
                mma_bf16(s[nt], ah0, ah1, ah2, ah3, bl[j][hh], bl[j][hh + 2]);
                mma_bf16(s[nt], al0, al1, al2, al3, bh[j][hh], bh[j][hh + 2]);
            }
        }

        // ---- mask + scale ----
        const int rg0 = t0 + r0, rg1 = t0 + r1;
#pragma unroll
        for (int nt = 0; nt < 4; nt++) {
            const int cg = k0 + nhalf * 32 + nt * 8 + 2 * t;
            s[nt][0] = (rg0 >= cg)     ? s[nt][0] * SCALING : -1e30f;
            s[nt][1] = (rg0 >= cg + 1) ? s[nt][1] * SCALING : -1e30f;
            s[nt][2] = (rg1 >= cg)     ? s[nt][2] * SCALING : -1e30f;
            s[nt][3] = (rg1 >= cg + 1) ? s[nt][3] * SCALING : -1e30f;
        }

        // ---- online softmax ----
        float mx0 = -1e30f, mx1 = -1e30f;
#pragma unroll
        for (int nt = 0; nt < 4; nt++) {
            mx0 = fmaxf(mx0, fmaxf(s[nt][0], s[nt][1]));
            mx1 = fmaxf(mx1, fmaxf(s[nt][2], s[nt][3]));
        }
        mx0 = fmaxf(mx0, __shfl_xor_sync(0xffffffffu, mx0, 1));
        mx0 = fmaxf(mx0, __shfl_xor_sync(0xffffffffu, mx0, 2));
        mx1 = fmaxf(mx1, __shfl_xor_sync(0xffffffffu, mx1, 1));
        mx1 = fmaxf(mx1, __shfl_xor_sync(0xffffffffu, mx1, 2));
        if (t == 0) { sWmax[nhalf * 64 + r0] = mx0; sWmax[nhalf * 64 + r1] = mx1; }
        __syncthreads();

        const float mn0 = fmaxf(sM[r0], fmaxf(sWmax[r0], sWmax[64 + r0]));
        const float mn1 = fmaxf(sM[r1], fmaxf(sWmax[r1], sWmax[64 + r1]));

        float sum0 = 0.f, sum1 = 0.f;
#pragma unroll
        for (int nt = 0; nt < 4; nt++) {
            s[nt][0] = __expf(s[nt][0] - mn0);
            s[nt][1] = __expf(s[nt][1] - mn0);
            s[nt][2] = __expf(s[nt][2] - mn1);
            s[nt][3] = __expf(s[nt][3] - mn1);
            sum0 += s[nt][0] + s[nt][1];
            sum1 += s[nt][2] + s[nt][3];
            // store P hi/lo (coll even -> 4B-aligned u32 stores)
            const int coll = nhalf * 32 + nt * 8 + 2 * t;
            __nv_bfloat16 h0, l0, h1, l1;
            split_hl(s[nt][0], h0, l0); split_hl(s[nt][1], h1, l1);
            *(uint32_t*)(sma + SPH + r0 * 144 + coll * 2) = pack2(h0, h1);
            *(uint32_t*)(sma + SPL + r0 * 144 + coll * 2) = pack2(l0, l1);
            split_hl(s[nt][2], h0, l0); split_hl(s[nt][3], h1, l1);
            *(uint32_t*)(sma + SPH + r1 * 144 + coll * 2) = pack2(h0, h1);
            *(uint32_t*)(sma + SPL + r1 * 144 + coll * 2) = pack2(l0, l1);
        }
        sum0 += __shfl_xor_sync(0xffffffffu, sum0, 1);
        sum0 += __shfl_xor_sync(0xffffffffu, sum0, 2);
        sum1 += __shfl_xor_sync(0xffffffffu, sum1, 1);
        sum1 += __shfl_xor_sync(0xffffffffu, sum1, 2);
        if (t == 0) { sWsum[nhalf * 64 + r0] = sum0; sWsum[nhalf * 64 + r1] = sum1; }
        __syncthreads();

        if (tid < 64) {
            const float mo = sM[tid];
            const float mn = fmaxf(mo, fmaxf(sWmax[tid], sWmax[64 + tid]));
            const float sc = __expf(mo - mn);
            sM[tid] = mn;
            sL[tid] = sL[tid] * sc + sWsum[tid] + sWsum[64 + tid];
            sScale[tid] = sc;
        }
        __syncthreads();

        // ---- O rescale + O += P @ V ----
        const float sc0 = sScale[r0], sc1 = sScale[r1];
#pragma unroll
        for (int nt = 0; nt < 8; nt++) {
            o[nt][0] *= sc0; o[nt][1] *= sc0;
            o[nt][2] *= sc1; o[nt][3] *= sc1;
        }

#pragma unroll
        for (int ks = 0; ks < 4; ks++) {
            const int kb = ks * 32 + kbL;
            uint32_t ph0, ph1, ph2, ph3, pl0, pl1, pl2, pl3;
            const int rP = (mrow + rowL) * 144 + kb;
            LDSM4(ph0, ph1, ph2, ph3, sb + SPH + rP);
            LDSM4(pl0, pl1, pl2, pl3, sb + SPL + rP);
#pragma unroll
            for (int j2 = 0; j2 < 4; j2++) {
                const int rV = (nhalf * 64 + j2 * 16 + rowL) * 144 + kb;
                uint32_t vh[4], vl[4];
                LDSM4(vh[0], vh[1], vh[2], vh[3], sb + SVH + rV);
                LDSM4(vl[0], vl[1], vl[2], vl[3], sb + SVL + rV);
#pragma unroll
                for (int hh = 0; hh < 2; hh++) {
                    float* acc = o[j2 * 2 + hh];
                    mma_bf16(acc, ph0, ph1, ph2, ph3, vh[hh], vh[hh + 2]);
                    mma_bf16(acc, ph0, ph1, ph2, ph3, vl[hh], vl[hh + 2]);
                    mma_bf16(acc, pl0, pl1, pl2, pl3, vh[hh], vh[hh + 2]);
                }
            }
        }
    }

    // ---- epilogue: normalize + write hi/lo planes ----
    const float il0 = 1.f / sL[r0];
    const float il1 = 1.f / sL[r1];
#pragma unroll
    for (int nt = 0; nt < 8; nt++) {
        const int col = h * D_V + nhalf * 64 + nt * 8 + 2 * t;
        const float v00 = o[nt][0] * il0, v01 = o[nt][1] * il0;
        const float v10 = o[nt][2] * il1, v11 = o[nt][3] * il1;
        __nv_bfloat16 h0, l0, h1, l1;
        split_hl(v00, h0, l0); split_hl(v01, h1, l1);
        ohi[((size_t)(t0 + r0) * (NH * D_V) + col) >> 1] = pack2(h0, h1);
        olo[((size_t)(t0 + r0) * (NH * D_V) + col) >> 1] = pack2(l0, l1);
        split_hl(v10, h0, l0); split_hl(v11, h1, l1);
        ohi[((size_t)(t0 + r1) * (NH * D_V) + col) >> 1] = pack2(h0, h1);
        olo[((size_t)(t0 + r1) * (NH * D_V) + col) >> 1] = pack2(l0, l1);
    }
}

// ---------------- launch ----------------
extern "C" void kernel_launch(void* const* d_in, const int* in_sizes, int n_in,
                              void* d_out, int out_size)
{
    const float* hidden    = (const float*)d_in[0];
    const int*   positions = (const int*)  d_in[1];
    const float* w_qkv_a   = (const float*)d_in[2];
    const float* gamma_q   = (const float*)d_in[3];
    const float* w_q_b     = (const float*)d_in[4];
    const float* gamma_kv  = (const float*)d_in[5];
    const float* w_kv_b    = (const float*)d_in[6];
    const float* w_o       = (const float*)d_in[7];
    float* out = (float*)d_out;

    float *qkv_a, *qbuf, *kvbuf, *kpe;
    __nv_bfloat16 *hid_h, *hid_l, *qn_h, *qn_l, *kvn_h, *kvn_l, *at_h, *at_l;
    __nv_bfloat16 *wa_h, *wa_l, *wqb_h, *wqb_l, *wkvb_h, *wkvb_l, *wo_h, *wo_l;
    __nv_bfloat16 *q_h, *q_l, *k_h, *k_l, *vt_h, *vt_l;
    cudaGetSymbolAddress((void**)&qkv_a, g_qkv_a);
    cudaGetSymbolAddress((void**)&qbuf,  g_qbuf);
    cudaGetSymbolAddress((void**)&kvbuf, g_kvbuf);
    cudaGetSymbolAddress((void**)&kpe,   g_kpe);
    cudaGetSymbolAddress((void**)&hid_h, g_hid_hi);  cudaGetSymbolAddress((void**)&hid_l, g_hid_lo);
    cudaGetSymbolAddress((void**)&qn_h,  g_qn_hi);   cudaGetSymbolAddress((void**)&qn_l,  g_qn_lo);
    cudaGetSymbolAddress((void**)&kvn_h, g_kvn_hi);  cudaGetSymbolAddress((void**)&kvn_l, g_kvn_lo);
    cudaGetSymbolAddress((void**)&at_h,  g_attn_hi); cudaGetSymbolAddress((void**)&at_l,  g_attn_lo);
    cudaGetSymbolAddress((void**)&wa_h,  g_wa_hi);   cudaGetSymbolAddress((void**)&wa_l,  g_wa_lo);
    cudaGetSymbolAddress((void**)&wqb_h, g_wqb_hi);  cudaGetSymbolAddress((void**)&wqb_l, g_wqb_lo);
    cudaGetSymbolAddress((void**)&wkvb_h,g_wkvb_hi); cudaGetSymbolAddress((void**)&wkvb_l,g_wkvb_lo);
    cudaGetSymbolAddress((void**)&wo_h,  g_wo_hi);   cudaGetSymbolAddress((void**)&wo_l,  g_wo_lo);
    cudaGetSymbolAddress((void**)&q_h,   g_q_hi);    cudaGetSymbolAddress((void**)&q_l,   g_q_lo);
    cudaGetSymbolAddress((void**)&k_h,   g_k_hi);    cudaGetSymbolAddress((void**)&k_l,   g_k_lo);
    cudaGetSymbolAddress((void**)&vt_h,  g_vt_hi);   cudaGetSymbolAddress((void**)&vt_l,  g_vt_lo);

    cudaFuncSetAttribute(gemm_hl, cudaFuncAttributeMaxDynamicSharedMemorySize, HL_SMEM);
    cudaFuncSetAttribute(attn_hl_kernel, cudaFuncAttributeMaxDynamicSharedMemorySize, ATT_SMEM);

    // 0) one-time conversions
    convert_hl_kernel<<<1184, 256>>>((const float2*)hidden,
        (uint32_t*)hid_h, (uint32_t*)hid_l, T_TOK * HID / 2);
    transpose_cvt_kernel<<<dim3(QKV_A_N / 32, HID / 32),      dim3(32, 8)>>>(w_qkv_a, wa_h,   wa_l,   HID,      QKV_A_N);
    transpose_cvt_kernel<<<dim3((NH*D_QK) / 32, Q_LORA / 32), dim3(32, 8)>>>(w_q_b,   wqb_h,  wqb_l,  Q_LORA,   NH * D_QK);
    transpose_cvt_kernel<<<dim3((NH*256) / 32, KV_LORA / 32), dim3(32, 8)>>>(w_kv_b,  wkvb_h, wkvb_l, KV_LORA,  NH * 256);
    transpose_cvt_kernel<<<dim3(HID / 32, (NH*D_V) / 32),     dim3(32, 8)>>>(w_o,     wo_h,   wo_l,   NH * D_V, HID);

    // 1) qkv_a = hidden @ w_qkv_a
    gemm_hl<<<dim3(QKV_A_N / 64, T_TOK / 256), 256, HL_SMEM>>>(
        hid_h, hid_l, wa_h, wa_l, qkv_a, T_TOK, QKV_A_N, HID);

    // 2) RMSNorm -> hi/lo
    rmsnorm_kernel<<<T_TOK, 256>>>(qkv_a, QKV_A_N, 0,      Q_LORA,  gamma_q,  qn_h,  qn_l);
    rmsnorm_kernel<<<T_TOK, 256>>>(qkv_a, QKV_A_N, Q_LORA, KV_LORA, gamma_kv, kvn_h, kvn_l);

    // 3) q = qn @ w_q_b  (fp32 out)
    gemm_hl<<<dim3((NH * D_QK) / 64, T_TOK / 256), 256, HL_SMEM>>>(
        qn_h, qn_l, wqb_h, wqb_l, qbuf, T_TOK, NH * D_QK, Q_LORA);

    // 4) kv = kvn @ w_kv_b  (fp32 out)
    gemm_hl<<<dim3((NH * 256) / 64, T_TOK / 256), 256, HL_SMEM>>>(
        kvn_h, kvn_l, wkvb_h, wkvb_l, kvbuf, T_TOK, NH * 256, KV_LORA);

    // 5) RoPE (fp32, in-place on qbuf + kpe out)
    rope_kernel<<<T_TOK, 256>>>(qbuf, qkv_a, kpe, positions);

    // 6) attention operand planes
    convert_hl_kernel<<<1184, 256>>>((const float2*)qbuf,
        (uint32_t*)q_h, (uint32_t*)q_l, T_TOK * NH * D_QK / 2);
    build_k_kernel<<<T_TOK, 256>>>(kvbuf, kpe, k_h, k_l);
    build_vt_kernel<<<dim3(T_TOK / 32, D_V / 32, NH), dim3(32, 8)>>>(kvbuf, vt_h, vt_l);

    // 7) attention -> hi/lo planes
    attn_hl_kernel<<<dim3(T_TOK / 64, NH), 256, ATT_SMEM>>>(
        q_h, q_l, k_h, k_l, vt_h, vt_l, (uint32_t*)at_h, (uint32_t*)at_l);

    // 8) out = attn @ w_o  (fp32 out)
    gemm_hl<<<dim3(HID / 64, T_TOK / 256), 256, HL_SMEM>>>(
        at_h, at_l, wo_h, wo_l, out, T_TOK, HID, NH * D_V);
}